// round 1
// baseline (speedup 1.0000x reference)
#include <cuda_runtime.h>

// SAR-ADC 4-bit successive approximation quantizer.
// x: [500000, 24] f32, W: [10] f32.
// Outputs (concatenated in d_out): q [500000,24] f32 (12M), Q [500000,24,4] f32 (48M).
//
// Constants from reference:
//   VDD = 1.8, NBITS = 4, VR = VDD/16 = 0.1125, VREF = VR, DELTA = 1e-30
//
// Unrolled recurrence (m descending from 9):
//   s3 = sign(x - W9*VREF + D)
//   s2 = sign(x - (W8*VREF + b3*W7*VR) + D)                  , b = (s+1)*0.5
//   s1 = sign(x - (W6*VREF + b2*W5*VR + b3*W4*VR) + D)
//   s0 = sign(x - (W3*VREF + b1*W2*VR + b2*W1*VR + b3*W0*VR) + D)
//   q  = b0*VR + b1*2VR + b2*4VR + b3*8VR

#define VRf    0.1125f
#define VREFf  0.1125f
#define DELTAf 1e-30f

__device__ __forceinline__ float sgn_d(float t) {
    // exact jnp.sign semantics: -1 / 0 / +1
    return (float)((t > 0.0f) - (t < 0.0f));
}

__global__ __launch_bounds__(256) void sar_adc_kernel(
    const float* __restrict__ x,
    const float* __restrict__ W,
    float* __restrict__ q_out,   // 12M floats
    float* __restrict__ Q_out,   // 48M floats
    int n4)                      // number of float4 elements (3,000,000)
{
    int i = blockIdx.x * blockDim.x + threadIdx.x;
    if (i >= n4) return;

    // Uniform weight loads — L1 broadcast, negligible cost.
    float w0 = __ldg(&W[0]), w1 = __ldg(&W[1]), w2 = __ldg(&W[2]);
    float w3 = __ldg(&W[3]), w4 = __ldg(&W[4]), w5 = __ldg(&W[5]);
    float w6 = __ldg(&W[6]), w7 = __ldg(&W[7]), w8 = __ldg(&W[8]);
    float w9 = __ldg(&W[9]);

    float4 xv = reinterpret_cast<const float4*>(x)[i];

    float qv[4];
    float4 Qv[4];

    float xe[4] = {xv.x, xv.y, xv.z, xv.w};

#pragma unroll
    for (int k = 0; k < 4; ++k) {
        float xx = xe[k];

        // bit 3
        float s3 = sgn_d(xx - w9 * VREFf + DELTAf);
        float b3 = (s3 + 1.0f) * 0.5f;
        // bit 2
        float bs2 = w8 * VREFf + b3 * (w7 * VRf);
        float s2 = sgn_d(xx - bs2 + DELTAf);
        float b2 = (s2 + 1.0f) * 0.5f;
        // bit 1
        float bs1 = w6 * VREFf + b2 * (w5 * VRf) + b3 * (w4 * VRf);
        float s1 = sgn_d(xx - bs1 + DELTAf);
        float b1 = (s1 + 1.0f) * 0.5f;
        // bit 0
        float bs0 = w3 * VREFf + b1 * (w2 * VRf) + b2 * (w1 * VRf) + b3 * (w0 * VRf);
        float s0 = sgn_d(xx - bs0 + DELTAf);
        float b0 = (s0 + 1.0f) * 0.5f;

        qv[k] = b0 * (VRf * 1.0f) + b1 * (VRf * 2.0f)
              + b2 * (VRf * 4.0f) + b3 * (VRf * 8.0f);

        // Q stacked along last axis with j ascending: [s0, s1, s2, s3]
        Qv[k] = make_float4(s0, s1, s2, s3);
    }

    reinterpret_cast<float4*>(q_out)[i] = make_float4(qv[0], qv[1], qv[2], qv[3]);

    float4* Qp = reinterpret_cast<float4*>(Q_out) + (size_t)i * 4;
    Qp[0] = Qv[0];
    Qp[1] = Qv[1];
    Qp[2] = Qv[2];
    Qp[3] = Qv[3];
}

extern "C" void kernel_launch(void* const* d_in, const int* in_sizes, int n_in,
                              void* d_out, int out_size) {
    const float* x = (const float*)d_in[0];
    const float* W = (const float*)d_in[1];

    int n = in_sizes[0];           // 12,000,000 elements of x
    int n4 = n / 4;                // 3,000,000 float4s

    float* q_out = (float*)d_out;          // first n floats
    float* Q_out = (float*)d_out + n;      // next 4*n floats

    int threads = 256;
    int blocks = (n4 + threads - 1) / threads;
    sar_adc_kernel<<<blocks, threads>>>(x, W, q_out, Q_out, n4);
}

// round 4
// speedup vs baseline: 1.2925x; 1.2925x over previous
#include <cuda_runtime.h>

// SAR-ADC 4-bit successive approximation quantizer.
// x: [500000, 24] f32 (12M elems), W: [10] f32.
// d_out: q [12M] f32 followed by Q [12M][4] f32.
//
// Coalescing-first layout: each warp owns 128 consecutive elements.
// Thread t handles elements warpbase + k*32 + t, k = 0..3, so every
// global access (x loads, q stores, Q float4 stores) is perfectly
// coalesced across the warp. This removes the 4x L1-wavefront inflation
// of the previous consecutive-float4-per-thread Q store pattern.

#define VRf    0.1125f
#define VREFf  0.1125f
#define DELTAf 1e-30f

__device__ __forceinline__ float sgn_d(float t) {
    // exact jnp.sign semantics: -1 / 0 / +1
    return (float)((t > 0.0f) - (t < 0.0f));
}

__global__ __launch_bounds__(256) void sar_adc_kernel(
    const float* __restrict__ x,
    const float* __restrict__ W,
    float* __restrict__ q_out,   // 12M floats
    float* __restrict__ Q_out,   // 48M floats (float4 per element)
    int n)                       // total elements (12,000,000; multiple of 128)
{
    const int tid     = blockIdx.x * blockDim.x + threadIdx.x;
    const int warp_id = tid >> 5;
    const int lane    = tid & 31;
    const int base    = warp_id * 128 + lane;   // element for k=0

    if (base + 96 >= n && base >= n) return;    // n is a multiple of 128; keeps codegen simple

    // Uniform weight loads — broadcast within warp, amortized over 4 elements.
    const float w0 = __ldg(&W[0]), w1 = __ldg(&W[1]), w2 = __ldg(&W[2]);
    const float w3 = __ldg(&W[3]), w4 = __ldg(&W[4]), w5 = __ldg(&W[5]);
    const float w6 = __ldg(&W[6]), w7 = __ldg(&W[7]), w8 = __ldg(&W[8]);
    const float w9 = __ldg(&W[9]);

    // Precompute shared subexpressions (uniform across elements).
    const float t3  = w9 * VREFf;
    const float c2  = w8 * VREFf, c2a = w7 * VRf;
    const float c1  = w6 * VREFf, c1a = w5 * VRf, c1b = w4 * VRf;
    const float c0  = w3 * VREFf, c0a = w2 * VRf, c0b = w1 * VRf, c0c = w0 * VRf;

    float xv[4];
#pragma unroll
    for (int k = 0; k < 4; ++k)
        xv[k] = __ldg(&x[base + k * 32]);

    float  qv[4];
    float4 Qv[4];

#pragma unroll
    for (int k = 0; k < 4; ++k) {
        const float xx = xv[k];

        // bit 3
        const float s3 = sgn_d(xx - t3 + DELTAf);
        const float b3 = (s3 + 1.0f) * 0.5f;
        // bit 2
        const float s2 = sgn_d(xx - (c2 + b3 * c2a) + DELTAf);
        const float b2 = (s2 + 1.0f) * 0.5f;
        // bit 1
        const float s1 = sgn_d(xx - (c1 + b2 * c1a + b3 * c1b) + DELTAf);
        const float b1 = (s1 + 1.0f) * 0.5f;
        // bit 0
        const float s0 = sgn_d(xx - (c0 + b1 * c0a + b2 * c0b + b3 * c0c) + DELTAf);
        const float b0 = (s0 + 1.0f) * 0.5f;

        qv[k] = b0 * (VRf * 1.0f) + b1 * (VRf * 2.0f)
              + b2 * (VRf * 4.0f) + b3 * (VRf * 8.0f);
        Qv[k] = make_float4(s0, s1, s2, s3);
    }

    // All stores perfectly coalesced: consecutive lanes -> consecutive addresses.
#pragma unroll
    for (int k = 0; k < 4; ++k)
        q_out[base + k * 32] = qv[k];

    float4* Qp = reinterpret_cast<float4*>(Q_out);
#pragma unroll
    for (int k = 0; k < 4; ++k)
        Qp[base + k * 32] = Qv[k];
}

extern "C" void kernel_launch(void* const* d_in, const int* in_sizes, int n_in,
                              void* d_out, int out_size) {
    const float* x = (const float*)d_in[0];
    const float* W = (const float*)d_in[1];

    const int n = in_sizes[0];            // 12,000,000 elements
    float* q_out = (float*)d_out;         // first n floats
    float* Q_out = (float*)d_out + n;     // next 4*n floats

    const int threads = 256;
    const int elems_per_block = threads * 4;   // 1024
    const int blocks = (n + elems_per_block - 1) / elems_per_block;
    sar_adc_kernel<<<blocks, threads>>>(x, W, q_out, Q_out, n);
}